// round 10
// baseline (speedup 1.0000x reference)
#include <cuda_runtime.h>
#include <cuda_fp16.h>
#include <math.h>
#include <stdint.h>

constexpr int NSEQ = 384;
constexpr int CIN  = 128;
constexpr int NH   = 4;
constexpr int CHD  = 32;
constexpr int NTOK = NSEQ * NSEQ;
constexpr float QSCALE = 0.17677669529663687f;  // 1/sqrt(32)
constexpr float LOG2E  = 1.4426950408889634f;

// ---- scratch ----
__device__ __half g_znh[NTOK * CIN];
__device__ __half g_qh [NTOK * CIN];   // pre-scaled by QSCALE*LOG2E
__device__ __half g_kh [NTOK * CIN];
__device__ __half g_vh [NTOK * CIN];
__device__ __half g_gh [NTOK * CIN];
__device__ __half g_ogh[NTOK * CIN];
__device__ __half g_trih[NH * NTOK];   // [h][q*NSEQ+k], pre-scaled by LOG2E

__device__ __forceinline__ uint32_t h2u(__half2 h) { return *(uint32_t*)&h; }
__device__ __forceinline__ float fexp2(float x) {
    float r; asm("ex2.approx.f32 %0, %1;" : "=f"(r) : "f"(x)); return r;
}
__device__ __forceinline__ uint32_t hexp2x2(uint32_t x) {
    uint32_t r; asm("ex2.approx.f16x2 %0, %1;" : "=r"(r) : "r"(x)); return r;
}

__device__ __forceinline__ void ldm_x4(uint32_t* r, const void* p) {
    uint32_t a = (uint32_t)__cvta_generic_to_shared(p);
    asm volatile("ldmatrix.sync.aligned.m8n8.x4.shared.b16 {%0,%1,%2,%3}, [%4];"
        : "=r"(r[0]), "=r"(r[1]), "=r"(r[2]), "=r"(r[3]) : "r"(a));
}
__device__ __forceinline__ void ldm_x4t(uint32_t* r, const void* p) {
    uint32_t a = (uint32_t)__cvta_generic_to_shared(p);
    asm volatile("ldmatrix.sync.aligned.m8n8.x4.trans.shared.b16 {%0,%1,%2,%3}, [%4];"
        : "=r"(r[0]), "=r"(r[1]), "=r"(r[2]), "=r"(r[3]) : "r"(a));
}
// D += A(16x16) * B(16x8), fp16 in, fp32 accum
__device__ __forceinline__ void mma16(float* d, const uint32_t* a, const uint32_t* b) {
    asm volatile(
        "mma.sync.aligned.m16n8k16.row.col.f32.f16.f16.f32 "
        "{%0,%1,%2,%3},{%4,%5,%6,%7},{%8,%9},{%0,%1,%2,%3};"
        : "+f"(d[0]), "+f"(d[1]), "+f"(d[2]), "+f"(d[3])
        : "r"(a[0]), "r"(a[1]), "r"(a[2]), "r"(a[3]), "r"(b[0]), "r"(b[1]));
}

// ============================================================
// Kernel 1: LayerNorm + tri. Warp per token.
// ============================================================
__global__ __launch_bounds__(256)
void ln_tri_kernel(const float* __restrict__ z,
                   const float* __restrict__ ln_w,
                   const float* __restrict__ ln_b,
                   const float* __restrict__ w_tri) {
    int warp = threadIdx.x >> 5, lane = threadIdx.x & 31;
    int t = blockIdx.x * 8 + warp;

    float4 x = *(const float4*)&z[(size_t)t * CIN + lane * 4];
    float v1 = x.x + x.y + x.z + x.w;
    float v2 = x.x * x.x + x.y * x.y + x.z * x.z + x.w * x.w;
    #pragma unroll
    for (int off = 16; off; off >>= 1) {
        v1 += __shfl_xor_sync(~0u, v1, off);
        v2 += __shfl_xor_sync(~0u, v2, off);
    }
    float mean = v1 * (1.0f / CIN);
    float var  = v2 * (1.0f / CIN) - mean * mean;
    float rs   = rsqrtf(var + 1e-5f);

    float4 w = *(const float4*)&ln_w[lane * 4];
    float4 b = *(const float4*)&ln_b[lane * 4];
    float4 zn;
    zn.x = (x.x - mean) * rs * w.x + b.x;
    zn.y = (x.y - mean) * rs * w.y + b.y;
    zn.z = (x.z - mean) * rs * w.z + b.z;
    zn.w = (x.w - mean) * rs * w.w + b.w;
    uint2 u = { h2u(__floats2half2_rn(zn.x, zn.y)), h2u(__floats2half2_rn(zn.z, zn.w)) };
    *(uint2*)&g_znh[(size_t)t * CIN + lane * 4] = u;

    float p[4] = {};
    float zc[4] = { zn.x, zn.y, zn.z, zn.w };
    #pragma unroll
    for (int cc = 0; cc < 4; cc++) {
        float4 wt = *(const float4*)&w_tri[(lane * 4 + cc) * NH];
        p[0] += zc[cc] * wt.x; p[1] += zc[cc] * wt.y;
        p[2] += zc[cc] * wt.z; p[3] += zc[cc] * wt.w;
    }
    #pragma unroll
    for (int off = 16; off; off >>= 1)
        #pragma unroll
        for (int h = 0; h < 4; h++) p[h] += __shfl_xor_sync(~0u, p[h], off);
    if (lane == 0)
        #pragma unroll
        for (int h = 0; h < 4; h++)
            g_trih[(size_t)h * NTOK + t] = __float2half(p[h] * LOG2E);
}

// ============================================================
// Kernel 2: fused 4-way projections, double-buffered B.
// ============================================================
constexpr int HS = 136;   // halves per smem row

__global__ __launch_bounds__(256, 2)
void proj_tc(const float* __restrict__ wq, const float* __restrict__ wk,
             const float* __restrict__ wv, const float* __restrict__ wg) {
    extern __shared__ __half smh[];
    __half* As = smh;                         // 128 x HS
    __half* Bbuf[2] = { smh + 128 * HS, smh + 2 * 128 * HS };
    int tid = threadIdx.x, lane = tid & 31, warp = tid >> 5;
    int g = lane >> 2, t = lane & 3;
    int m0 = blockIdx.x * 128;
    const float* Ws[4] = { wq, wk, wv, wg };

    #pragma unroll
    for (int e = 0; e < 8; e++) {
        int f = tid + e * 256;
        int row = f >> 4, c8 = (f & 15) * 8;
        *(uint4*)&As[row * HS + c8] = *(const uint4*)&g_znh[(size_t)(m0 + row) * CIN + c8];
    }
    #pragma unroll
    for (int e = 0; e < 16; e++) {
        int f = tid + e * 256;
        int row = f >> 5, c4 = (f & 31) * 4;
        float4 v = *(const float4*)&wq[(size_t)row * CIN + c4];
        uint2 u = { h2u(__floats2half2_rn(v.x, v.y)), h2u(__floats2half2_rn(v.z, v.w)) };
        *(uint2*)&Bbuf[0][row * HS + c4] = u;
    }
    __syncthreads();

    int wm = warp >> 1, wn = warp & 1;   // 4x2, warp tile 32m x 64n
    const float QS2 = QSCALE * LOG2E;

    for (int sel = 0; sel < 4; sel++) {
        __half* Bs = Bbuf[sel & 1];
        __half* Bn = Bbuf[(sel + 1) & 1];

        if (sel < 3) {
            const float* W = Ws[sel + 1];
            #pragma unroll
            for (int e = 0; e < 16; e++) {
                int f = tid + e * 256;
                int row = f >> 5, c4 = (f & 31) * 4;
                float4 v = *(const float4*)&W[(size_t)row * CIN + c4];
                uint2 u = { h2u(__floats2half2_rn(v.x, v.y)), h2u(__floats2half2_rn(v.z, v.w)) };
                *(uint2*)&Bn[row * HS + c4] = u;
            }
        }

        float acc[2][8][4] = {};
        #pragma unroll
        for (int kc2 = 0; kc2 < 4; kc2++) {
            uint32_t bf[8][4];
            #pragma unroll
            for (int nt = 0; nt < 8; nt++)
                ldm_x4t(bf[nt], &Bs[(kc2 * 32 + lane) * HS + wn * 64 + nt * 8]);
            #pragma unroll
            for (int kk = 0; kk < 2; kk++) {
                uint32_t af[2][4];
                #pragma unroll
                for (int mt = 0; mt < 2; mt++)
                    ldm_x4(af[mt], &As[(wm * 32 + mt * 16 + (lane & 15)) * HS
                                       + (kc2 * 2 + kk) * 16 + (lane >> 4) * 8]);
                #pragma unroll
                for (int nt = 0; nt < 8; nt++) {
                    mma16(acc[0][nt], af[0], &bf[nt][kk * 2]);
                    mma16(acc[1][nt], af[1], &bf[nt][kk * 2]);
                }
            }
        }

        #pragma unroll
        for (int mt = 0; mt < 2; mt++)
            #pragma unroll
            for (int nt = 0; nt < 8; nt++)
                #pragma unroll
                for (int hf = 0; hf < 2; hf++) {
                    int gm  = m0 + wm * 32 + mt * 16 + g + hf * 8;
                    int col = wn * 64 + nt * 8 + 2 * t;
                    float c0 = acc[mt][nt][hf * 2 + 0], c1 = acc[mt][nt][hf * 2 + 1];
                    size_t idx = (size_t)gm * CIN + col;
                    if (sel == 0)
                        *(uint32_t*)&g_qh[idx] = h2u(__floats2half2_rn(c0 * QS2, c1 * QS2));
                    else if (sel == 1)
                        *(uint32_t*)&g_kh[idx] = h2u(__floats2half2_rn(c0, c1));
                    else if (sel == 2)
                        *(uint32_t*)&g_vh[idx] = h2u(__floats2half2_rn(c0, c1));
                    else
                        *(uint32_t*)&g_gh[idx] = h2u(__floats2half2_rn(
                            1.0f / (1.0f + __expf(-c0)), 1.0f / (1.0f + __expf(-c1))));
                }
        __syncthreads();
    }
}

// ============================================================
// Kernel 3: attention. fp16 mma flash tiles, 48-k chunks.
// Tri bias prefetched one chunk ahead (hides L2 latency);
// softmax exp via ex2.approx.f16x2 (output IS the P fragment);
// row sums via all-ones mma column.
// ============================================================
constexpr int KSS = 40;   // halves per K/V row

__global__ __launch_bounds__(256, 2)
void attn_tc(const float* __restrict__ mask) {
    int i = blockIdx.x, h = blockIdx.y;
    extern __shared__ __half smh[];
    __half* Ks  = smh;                  // 384 x 40
    __half* Vs  = smh + NSEQ * KSS;     // 384 x 40
    float*  bsm = (float*)(smh + 2 * NSEQ * KSS);  // 384

    int tid = threadIdx.x, lane = tid & 31, warp = tid >> 5;
    int g = lane >> 2, t = lane & 3;

    const __half* gK = g_kh + (size_t)(i * NSEQ) * CIN + h * CHD;
    const __half* gV = g_vh + (size_t)(i * NSEQ) * CIN + h * CHD;
    #pragma unroll
    for (int e = 0; e < 12; e++) {
        int f = tid + e * 256;              // 3072 4-half units
        int row = f >> 3, c4 = (f & 7) * 4;
        *(uint2*)&Ks[row * KSS + c4] = *(const uint2*)&gK[(size_t)row * CIN + c4];
        *(uint2*)&Vs[row * KSS + c4] = *(const uint2*)&gV[(size_t)row * CIN + c4];
    }
    {
        int k = tid;
        if (k < NSEQ) bsm[k] = LOG2E * 1e9f * (mask[i * NSEQ + k] - 1.0f);
        k += 256;
        if (k < NSEQ) bsm[k] = LOG2E * 1e9f * (mask[i * NSEQ + k] - 1.0f);
    }
    __syncthreads();

    const __half* trih = g_trih + (size_t)h * NTOK;
    const uint32_t onesb[2] = { 0x3C003C00u, 0x3C003C00u };   // fp16 1.0 x2

    for (int tile = warp; tile < 24; tile += 8) {
        int q0 = tile * 16;
        int qa = q0 + g, qb = qa + 8;
        const __half* triA = trih + (size_t)qa * NSEQ;
        const __half* triB = trih + (size_t)qb * NSEQ;

        const __half* gQ = g_qh + (size_t)(i * NSEQ + q0) * CIN + h * CHD;
        uint32_t qa_[2][4];
        #pragma unroll
        for (int kc = 0; kc < 2; kc++) {
            qa_[kc][0] = *(const uint32_t*)&gQ[(size_t)g * CIN + kc * 16 + 2 * t];
            qa_[kc][1] = *(const uint32_t*)&gQ[(size_t)(g + 8) * CIN + kc * 16 + 2 * t];
            qa_[kc][2] = *(const uint32_t*)&gQ[(size_t)g * CIN + kc * 16 + 2 * t + 8];
            qa_[kc][3] = *(const uint32_t*)&gQ[(size_t)(g + 8) * CIN + kc * 16 + 2 * t + 8];
        }

        float M0 = -1e30f, M1 = -1e30f;
        float O[5][4] = {};    // O[4] = row-sum column (P @ ones)

        // prefetch tri for chunk 0
        uint32_t tb0[6], tb1[6];
        #pragma unroll
        for (int nt = 0; nt < 6; nt++) {
            int k = nt * 8 + 2 * t;
            tb0[nt] = *(const uint32_t*)&triA[k];
            tb1[nt] = *(const uint32_t*)&triB[k];
        }

        #pragma unroll
        for (int ch = 0; ch < 8; ch++) {      // 48-k chunks
            int k0c = ch * 48;

            // ---- QK scores (log2 domain) ----
            float s[6][4];
            #pragma unroll
            for (int nt = 0; nt < 6; nt++) {
                s[nt][0] = s[nt][1] = s[nt][2] = s[nt][3] = 0.f;
                uint32_t bf[4];
                ldm_x4(bf, &Ks[(k0c + nt * 8 + (lane & 7)) * KSS + (lane >> 3) * 8]);
                mma16(s[nt], qa_[0], &bf[0]);
                mma16(s[nt], qa_[1], &bf[2]);
            }

            // ---- prefetch next chunk's tri (lands during softmax+AV) ----
            uint32_t tn0[6], tn1[6];
            if (ch < 7) {
                #pragma unroll
                for (int nt = 0; nt < 6; nt++) {
                    int k = k0c + 48 + nt * 8 + 2 * t;
                    tn0[nt] = *(const uint32_t*)&triA[k];
                    tn1[nt] = *(const uint32_t*)&triB[k];
                }
            }

            // ---- biases (prefetched tri) + chunk max ----
            float cm0 = -1e30f, cm1 = -1e30f;
            #pragma unroll
            for (int nt = 0; nt < 6; nt++) {
                int k = k0c + nt * 8 + 2 * t;
                float2 bb = *(const float2*)&bsm[k];
                float2 t0 = __half22float2(*(const __half2*)&tb0[nt]);
                float2 t1 = __half22float2(*(const __half2*)&tb1[nt]);
                s[nt][0] += bb.x + t0.x; s[nt][1] += bb.y + t0.y;
                s[nt][2] += bb.x + t1.x; s[nt][3] += bb.y + t1.y;
                cm0 = fmaxf(cm0, fmaxf(s[nt][0], s[nt][1]));
                cm1 = fmaxf(cm1, fmaxf(s[nt][2], s[nt][3]));
            }
            cm0 = fmaxf(cm0, __shfl_xor_sync(~0u, cm0, 1));
            cm0 = fmaxf(cm0, __shfl_xor_sync(~0u, cm0, 2));
            cm1 = fmaxf(cm1, __shfl_xor_sync(~0u, cm1, 1));
            cm1 = fmaxf(cm1, __shfl_xor_sync(~0u, cm1, 2));

            // ---- online rescale (O[4] sum column rescales with O) ----
            float Mn0 = fmaxf(M0, cm0), Mn1 = fmaxf(M1, cm1);
            float al0 = fexp2(M0 - Mn0), al1 = fexp2(M1 - Mn1);
            M0 = Mn0; M1 = Mn1;
            #pragma unroll
            for (int ct = 0; ct < 5; ct++) {
                O[ct][0] *= al0; O[ct][1] *= al0;
                O[ct][2] *= al1; O[ct][3] *= al1;
            }

            // ---- exp2 in f16x2: output IS the P A-fragment ----
            uint32_t e[6][2];
            #pragma unroll
            for (int nt = 0; nt < 6; nt++) {
                e[nt][0] = hexp2x2(h2u(__floats2half2_rn(s[nt][0] - M0, s[nt][1] - M0)));
                e[nt][1] = hexp2x2(h2u(__floats2half2_rn(s[nt][2] - M1, s[nt][3] - M1)));
            }

            // ---- AV + ones-column sum ----
            #pragma unroll
            for (int j = 0; j < 3; j++) {       // k16 steps
                uint32_t pa[4] = { e[2 * j][0], e[2 * j][1],
                                   e[2 * j + 1][0], e[2 * j + 1][1] };
                #pragma unroll
                for (int ct2 = 0; ct2 < 2; ct2++) {
                    uint32_t vb[4];
                    ldm_x4t(vb, &Vs[(k0c + j * 16 + (lane & 15)) * KSS
                                    + ct2 * 16 + (lane >> 4) * 8]);
                    mma16(O[ct2 * 2 + 0], pa, &vb[0]);
                    mma16(O[ct2 * 2 + 1], pa, &vb[2]);
                }
                mma16(O[4], pa, onesb);         // row sums
            }

            // rotate prefetch buffers
            #pragma unroll
            for (int nt = 0; nt < 6; nt++) { tb0[nt] = tn0[nt]; tb1[nt] = tn1[nt]; }
        }

        // ---- normalize (l = ones column), gate, store og ----
        float inv0 = 1.0f / O[4][0], inv1 = 1.0f / O[4][2];
        #pragma unroll
        for (int ct = 0; ct < 4; ct++) {
            int c = ct * 8 + 2 * t;
            size_t idx0 = (size_t)(i * NSEQ + q0 + g) * CIN + h * CHD + c;
            size_t idx1 = idx0 + (size_t)8 * CIN;
            float2 gg0 = __half22float2(*(const __half2*)&g_gh[idx0]);
            float2 gg1 = __half22float2(*(const __half2*)&g_gh[idx1]);
            *(uint32_t*)&g_ogh[idx0] = h2u(__floats2half2_rn(
                O[ct][0] * inv0 * gg0.x, O[ct][1] * inv0 * gg0.y));
            *(uint32_t*)&g_ogh[idx1] = h2u(__floats2half2_rn(
                O[ct][2] * inv1 * gg1.x, O[ct][3] * inv1 * gg1.y));
        }
    }
}

// ============================================================
// Kernel 4: out = og @ wo, fp16 mma. og already half.
// ============================================================
__global__ __launch_bounds__(256, 2)
void out_tc(const float* __restrict__ wo, float* __restrict__ out) {
    extern __shared__ __half smh[];
    __half* As = smh;
    __half* Bs = smh + 128 * HS;
    int tid = threadIdx.x, lane = tid & 31, warp = tid >> 5;
    int g = lane >> 2, t = lane & 3;
    int m0 = blockIdx.x * 128;

    #pragma unroll
    for (int e = 0; e < 8; e++) {
        int f = tid + e * 256;
        int row = f >> 4, c8 = (f & 15) * 8;
        *(uint4*)&As[row * HS + c8] = *(const uint4*)&g_ogh[(size_t)(m0 + row) * CIN + c8];
    }
    #pragma unroll
    for (int e = 0; e < 16; e++) {
        int f = tid + e * 256;
        int row = f >> 5, c4 = (f & 31) * 4;
        float4 vb = *(const float4*)&wo[(size_t)row * CIN + c4];
        uint2 ub = { h2u(__floats2half2_rn(vb.x, vb.y)), h2u(__floats2half2_rn(vb.z, vb.w)) };
        *(uint2*)&Bs[row * HS + c4] = ub;
    }
    __syncthreads();

    int wm = warp >> 1, wn = warp & 1;
    float acc[2][8][4] = {};
    #pragma unroll
    for (int kc2 = 0; kc2 < 4; kc2++) {
        uint32_t bf[8][4];
        #pragma unroll
        for (int nt = 0; nt < 8; nt++)
            ldm_x4t(bf[nt], &Bs[(kc2 * 32 + lane) * HS + wn * 64 + nt * 8]);
        #pragma unroll
        for (int kk = 0; kk < 2; kk++) {
            uint32_t af[2][4];
            #pragma unroll
            for (int mt = 0; mt < 2; mt++)
                ldm_x4(af[mt], &As[(wm * 32 + mt * 16 + (lane & 15)) * HS
                                   + (kc2 * 2 + kk) * 16 + (lane >> 4) * 8]);
            #pragma unroll
            for (int nt = 0; nt < 8; nt++) {
                mma16(acc[0][nt], af[0], &bf[nt][kk * 2]);
                mma16(acc[1][nt], af[1], &bf[nt][kk * 2]);
            }
        }
    }
    #pragma unroll
    for (int mt = 0; mt < 2; mt++)
        #pragma unroll
        for (int nt = 0; nt < 8; nt++)
            #pragma unroll
            for (int hf = 0; hf < 2; hf++) {
                int gm  = m0 + wm * 32 + mt * 16 + g + hf * 8;
                int col = wn * 64 + nt * 8 + 2 * t;
                float2 o = { acc[mt][nt][hf * 2 + 0], acc[mt][nt][hf * 2 + 1] };
                *(float2*)&out[(size_t)gm * CIN + col] = o;
            }
}

// ============================================================
extern "C" void kernel_launch(void* const* d_in, const int* in_sizes, int n_in,
                              void* d_out, int out_size) {
    const float* z     = (const float*)d_in[0];
    const float* mask  = (const float*)d_in[1];
    const float* ln_w  = (const float*)d_in[2];
    const float* ln_b  = (const float*)d_in[3];
    const float* w_tri = (const float*)d_in[4];
    const float* wq    = (const float*)d_in[5];
    const float* wk    = (const float*)d_in[6];
    const float* wv    = (const float*)d_in[7];
    const float* wg    = (const float*)d_in[8];
    const float* wo    = (const float*)d_in[9];
    float* out = (float*)d_out;

    ln_tri_kernel<<<NTOK / 8, 256>>>(z, ln_w, ln_b, w_tri);

    size_t proj_smem = (size_t)(3 * 128 * HS) * sizeof(__half);  // 104448
    cudaFuncSetAttribute(proj_tc, cudaFuncAttributeMaxDynamicSharedMemorySize, (int)proj_smem);
    proj_tc<<<NTOK / 128, 256, proj_smem>>>(wq, wk, wv, wg);

    size_t att_smem = (size_t)(2 * NSEQ * KSS) * sizeof(__half) + NSEQ * sizeof(float); // 62976
    cudaFuncSetAttribute(attn_tc, cudaFuncAttributeMaxDynamicSharedMemorySize, (int)att_smem);
    dim3 ga(NSEQ, NH);
    attn_tc<<<ga, 256, att_smem>>>(mask);

    size_t out_smem = (size_t)(2 * 128 * HS) * sizeof(__half);   // 69632
    cudaFuncSetAttribute(out_tc, cudaFuncAttributeMaxDynamicSharedMemorySize, (int)out_smem);
    out_tc<<<NTOK / 128, 256, out_smem>>>(wo, out);
}

// round 11
// speedup vs baseline: 1.0575x; 1.0575x over previous
#include <cuda_runtime.h>
#include <cuda_fp16.h>
#include <math.h>
#include <stdint.h>

constexpr int NSEQ = 384;
constexpr int CIN  = 128;
constexpr int NH   = 4;
constexpr int CHD  = 32;
constexpr int NTOK = NSEQ * NSEQ;
constexpr float QSCALE = 0.17677669529663687f;  // 1/sqrt(32)
constexpr float LOG2E  = 1.4426950408889634f;

// ---- scratch ----
__device__ __half g_qh [NTOK * CIN];   // pre-scaled by QSCALE*LOG2E
__device__ __half g_kh [NTOK * CIN];
__device__ __half g_vh [NTOK * CIN];
__device__ __half g_gh [NTOK * CIN];
__device__ __half g_ogh[NTOK * CIN];
__device__ __half g_trih[NH * NTOK];   // [h][q*NSEQ+k], pre-scaled by LOG2E

__device__ __forceinline__ uint32_t h2u(__half2 h) { return *(uint32_t*)&h; }
__device__ __forceinline__ float fexp2(float x) {
    float r; asm("ex2.approx.f32 %0, %1;" : "=f"(r) : "f"(x)); return r;
}
__device__ __forceinline__ uint32_t hexp2x2(uint32_t x) {
    uint32_t r; asm("ex2.approx.f16x2 %0, %1;" : "=r"(r) : "r"(x)); return r;
}

__device__ __forceinline__ void ldm_x4(uint32_t* r, const void* p) {
    uint32_t a = (uint32_t)__cvta_generic_to_shared(p);
    asm volatile("ldmatrix.sync.aligned.m8n8.x4.shared.b16 {%0,%1,%2,%3}, [%4];"
        : "=r"(r[0]), "=r"(r[1]), "=r"(r[2]), "=r"(r[3]) : "r"(a));
}
__device__ __forceinline__ void ldm_x4t(uint32_t* r, const void* p) {
    uint32_t a = (uint32_t)__cvta_generic_to_shared(p);
    asm volatile("ldmatrix.sync.aligned.m8n8.x4.trans.shared.b16 {%0,%1,%2,%3}, [%4];"
        : "=r"(r[0]), "=r"(r[1]), "=r"(r[2]), "=r"(r[3]) : "r"(a));
}
// D += A(16x16) * B(16x8), fp16 in, fp32 accum
__device__ __forceinline__ void mma16(float* d, const uint32_t* a, const uint32_t* b) {
    asm volatile(
        "mma.sync.aligned.m16n8k16.row.col.f32.f16.f16.f32 "
        "{%0,%1,%2,%3},{%4,%5,%6,%7},{%8,%9},{%0,%1,%2,%3};"
        : "+f"(d[0]), "+f"(d[1]), "+f"(d[2]), "+f"(d[3])
        : "r"(a[0]), "r"(a[1]), "r"(a[2]), "r"(a[3]), "r"(b[0]), "r"(b[1]));
}

// ============================================================
// Kernel 1: fused LayerNorm + tri + 4-way projections.
// CTA owns a 128-token stripe. LN computed in the prologue
// (warp = 16 rows, lane = 4 channels) straight into the smem
// A-tile; tri emitted from the same registers. B double-buffered
// across the 4 weight matrices.
// ============================================================
constexpr int HS = 136;   // halves per smem row

__global__ __launch_bounds__(256, 2)
void proj_tc(const float* __restrict__ z,
             const float* __restrict__ ln_w,
             const float* __restrict__ ln_b,
             const float* __restrict__ w_tri,
             const float* __restrict__ wq, const float* __restrict__ wk,
             const float* __restrict__ wv, const float* __restrict__ wg) {
    extern __shared__ __half smh[];
    __half* As = smh;                         // 128 x HS
    __half* Bbuf[2] = { smh + 128 * HS, smh + 2 * 128 * HS };
    int tid = threadIdx.x, lane = tid & 31, warp = tid >> 5;
    int g = lane >> 2, t = lane & 3;
    int m0 = blockIdx.x * 128;
    const float* Ws[4] = { wq, wk, wv, wg };

    // ---- LN + tri for this warp's 16 rows; zn-half -> As ----
    {
        float4 w4 = *(const float4*)&ln_w[lane * 4];
        float4 b4 = *(const float4*)&ln_b[lane * 4];
        float4 wt[4];
        #pragma unroll
        for (int cc = 0; cc < 4; cc++)
            wt[cc] = *(const float4*)&w_tri[(lane * 4 + cc) * NH];

        for (int r = 0; r < 16; r++) {
            int row = warp * 16 + r;
            float4 x = *(const float4*)&z[(size_t)(m0 + row) * CIN + lane * 4];
            float v1 = x.x + x.y + x.z + x.w;
            float v2 = x.x * x.x + x.y * x.y + x.z * x.z + x.w * x.w;
            #pragma unroll
            for (int off = 16; off; off >>= 1) {
                v1 += __shfl_xor_sync(~0u, v1, off);
                v2 += __shfl_xor_sync(~0u, v2, off);
            }
            float mean = v1 * (1.0f / CIN);
            float var  = v2 * (1.0f / CIN) - mean * mean;
            float rs   = rsqrtf(var + 1e-5f);
            float zn0 = (x.x - mean) * rs * w4.x + b4.x;
            float zn1 = (x.y - mean) * rs * w4.y + b4.y;
            float zn2 = (x.z - mean) * rs * w4.z + b4.z;
            float zn3 = (x.w - mean) * rs * w4.w + b4.w;
            uint2 u = { h2u(__floats2half2_rn(zn0, zn1)), h2u(__floats2half2_rn(zn2, zn3)) };
            *(uint2*)&As[row * HS + lane * 4] = u;

            float p[4];
            #pragma unroll
            for (int h = 0; h < 4; h++)
                p[h] = zn0 * wt[0].x * 0.0f;   // init below properly
            p[0] = zn0 * wt[0].x + zn1 * wt[1].x + zn2 * wt[2].x + zn3 * wt[3].x;
            p[1] = zn0 * wt[0].y + zn1 * wt[1].y + zn2 * wt[2].y + zn3 * wt[3].y;
            p[2] = zn0 * wt[0].z + zn1 * wt[1].z + zn2 * wt[2].z + zn3 * wt[3].z;
            p[3] = zn0 * wt[0].w + zn1 * wt[1].w + zn2 * wt[2].w + zn3 * wt[3].w;
            #pragma unroll
            for (int off = 16; off; off >>= 1)
                #pragma unroll
                for (int h = 0; h < 4; h++) p[h] += __shfl_xor_sync(~0u, p[h], off);
            if (lane == 0) {
                #pragma unroll
                for (int h = 0; h < 4; h++)
                    g_trih[(size_t)h * NTOK + m0 + row] = __float2half(p[h] * LOG2E);
            }
        }
    }

    // ---- B0: wq ----
    #pragma unroll
    for (int e = 0; e < 16; e++) {
        int f = tid + e * 256;
        int row = f >> 5, c4 = (f & 31) * 4;
        float4 v = *(const float4*)&wq[(size_t)row * CIN + c4];
        uint2 u = { h2u(__floats2half2_rn(v.x, v.y)), h2u(__floats2half2_rn(v.z, v.w)) };
        *(uint2*)&Bbuf[0][row * HS + c4] = u;
    }
    __syncthreads();

    int wm = warp >> 1, wn = warp & 1;   // 4x2, warp tile 32m x 64n
    const float QS2 = QSCALE * LOG2E;

    for (int sel = 0; sel < 4; sel++) {
        __half* Bs = Bbuf[sel & 1];
        __half* Bn = Bbuf[(sel + 1) & 1];

        if (sel < 3) {
            const float* W = Ws[sel + 1];
            #pragma unroll
            for (int e = 0; e < 16; e++) {
                int f = tid + e * 256;
                int row = f >> 5, c4 = (f & 31) * 4;
                float4 v = *(const float4*)&W[(size_t)row * CIN + c4];
                uint2 u = { h2u(__floats2half2_rn(v.x, v.y)), h2u(__floats2half2_rn(v.z, v.w)) };
                *(uint2*)&Bn[row * HS + c4] = u;
            }
        }

        float acc[2][8][4] = {};
        #pragma unroll
        for (int kc2 = 0; kc2 < 4; kc2++) {
            uint32_t bf[8][4];
            #pragma unroll
            for (int nt = 0; nt < 8; nt++)
                ldm_x4t(bf[nt], &Bs[(kc2 * 32 + lane) * HS + wn * 64 + nt * 8]);
            #pragma unroll
            for (int kk = 0; kk < 2; kk++) {
                uint32_t af[2][4];
                #pragma unroll
                for (int mt = 0; mt < 2; mt++)
                    ldm_x4(af[mt], &As[(wm * 32 + mt * 16 + (lane & 15)) * HS
                                       + (kc2 * 2 + kk) * 16 + (lane >> 4) * 8]);
                #pragma unroll
                for (int nt = 0; nt < 8; nt++) {
                    mma16(acc[0][nt], af[0], &bf[nt][kk * 2]);
                    mma16(acc[1][nt], af[1], &bf[nt][kk * 2]);
                }
            }
        }

        #pragma unroll
        for (int mt = 0; mt < 2; mt++)
            #pragma unroll
            for (int nt = 0; nt < 8; nt++)
                #pragma unroll
                for (int hf = 0; hf < 2; hf++) {
                    int gm  = m0 + wm * 32 + mt * 16 + g + hf * 8;
                    int col = wn * 64 + nt * 8 + 2 * t;
                    float c0 = acc[mt][nt][hf * 2 + 0], c1 = acc[mt][nt][hf * 2 + 1];
                    size_t idx = (size_t)gm * CIN + col;
                    if (sel == 0)
                        *(uint32_t*)&g_qh[idx] = h2u(__floats2half2_rn(c0 * QS2, c1 * QS2));
                    else if (sel == 1)
                        *(uint32_t*)&g_kh[idx] = h2u(__floats2half2_rn(c0, c1));
                    else if (sel == 2)
                        *(uint32_t*)&g_vh[idx] = h2u(__floats2half2_rn(c0, c1));
                    else
                        *(uint32_t*)&g_gh[idx] = h2u(__floats2half2_rn(
                            1.0f / (1.0f + __expf(-c0)), 1.0f / (1.0f + __expf(-c1))));
                }
        __syncthreads();
    }
}

// ============================================================
// Kernel 2: attention. fp16 mma flash tiles, 48-k chunks,
// tri prefetch one chunk ahead, ex2.approx.f16x2 softmax,
// ones-column row sums. (unchanged from R10)
// ============================================================
constexpr int KSS = 40;   // halves per K/V row

__global__ __launch_bounds__(256, 2)
void attn_tc(const float* __restrict__ mask) {
    int i = blockIdx.x, h = blockIdx.y;
    extern __shared__ __half smh[];
    __half* Ks  = smh;                  // 384 x 40
    __half* Vs  = smh + NSEQ * KSS;     // 384 x 40
    float*  bsm = (float*)(smh + 2 * NSEQ * KSS);  // 384

    int tid = threadIdx.x, lane = tid & 31, warp = tid >> 5;
    int g = lane >> 2, t = lane & 3;

    const __half* gK = g_kh + (size_t)(i * NSEQ) * CIN + h * CHD;
    const __half* gV = g_vh + (size_t)(i * NSEQ) * CIN + h * CHD;
    #pragma unroll
    for (int e = 0; e < 12; e++) {
        int f = tid + e * 256;              // 3072 4-half units
        int row = f >> 3, c4 = (f & 7) * 4;
        *(uint2*)&Ks[row * KSS + c4] = *(const uint2*)&gK[(size_t)row * CIN + c4];
        *(uint2*)&Vs[row * KSS + c4] = *(const uint2*)&gV[(size_t)row * CIN + c4];
    }
    {
        int k = tid;
        if (k < NSEQ) bsm[k] = LOG2E * 1e9f * (mask[i * NSEQ + k] - 1.0f);
        k += 256;
        if (k < NSEQ) bsm[k] = LOG2E * 1e9f * (mask[i * NSEQ + k] - 1.0f);
    }
    __syncthreads();

    const __half* trih = g_trih + (size_t)h * NTOK;
    const uint32_t onesb[2] = { 0x3C003C00u, 0x3C003C00u };   // fp16 1.0 x2

    for (int tile = warp; tile < 24; tile += 8) {
        int q0 = tile * 16;
        int qa = q0 + g, qb = qa + 8;
        const __half* triA = trih + (size_t)qa * NSEQ;
        const __half* triB = trih + (size_t)qb * NSEQ;

        const __half* gQ = g_qh + (size_t)(i * NSEQ + q0) * CIN + h * CHD;
        uint32_t qa_[2][4];
        #pragma unroll
        for (int kc = 0; kc < 2; kc++) {
            qa_[kc][0] = *(const uint32_t*)&gQ[(size_t)g * CIN + kc * 16 + 2 * t];
            qa_[kc][1] = *(const uint32_t*)&gQ[(size_t)(g + 8) * CIN + kc * 16 + 2 * t];
            qa_[kc][2] = *(const uint32_t*)&gQ[(size_t)g * CIN + kc * 16 + 2 * t + 8];
            qa_[kc][3] = *(const uint32_t*)&gQ[(size_t)(g + 8) * CIN + kc * 16 + 2 * t + 8];
        }

        float M0 = -1e30f, M1 = -1e30f;
        float O[5][4] = {};    // O[4] = row-sum column (P @ ones)

        // prefetch tri for chunk 0
        uint32_t tb0[6], tb1[6];
        #pragma unroll
        for (int nt = 0; nt < 6; nt++) {
            int k = nt * 8 + 2 * t;
            tb0[nt] = *(const uint32_t*)&triA[k];
            tb1[nt] = *(const uint32_t*)&triB[k];
        }

        #pragma unroll
        for (int ch = 0; ch < 8; ch++) {      // 48-k chunks
            int k0c = ch * 48;

            // ---- QK scores (log2 domain) ----
            float s[6][4];
            #pragma unroll
            for (int nt = 0; nt < 6; nt++) {
                s[nt][0] = s[nt][1] = s[nt][2] = s[nt][3] = 0.f;
                uint32_t bf[4];
                ldm_x4(bf, &Ks[(k0c + nt * 8 + (lane & 7)) * KSS + (lane >> 3) * 8]);
                mma16(s[nt], qa_[0], &bf[0]);
                mma16(s[nt], qa_[1], &bf[2]);
            }

            // ---- prefetch next chunk's tri ----
            uint32_t tn0[6], tn1[6];
            if (ch < 7) {
                #pragma unroll
                for (int nt = 0; nt < 6; nt++) {
                    int k = k0c + 48 + nt * 8 + 2 * t;
                    tn0[nt] = *(const uint32_t*)&triA[k];
                    tn1[nt] = *(const uint32_t*)&triB[k];
                }
            }

            // ---- biases + chunk max ----
            float cm0 = -1e30f, cm1 = -1e30f;
            #pragma unroll
            for (int nt = 0; nt < 6; nt++) {
                int k = k0c + nt * 8 + 2 * t;
                float2 bb = *(const float2*)&bsm[k];
                float2 t0 = __half22float2(*(const __half2*)&tb0[nt]);
                float2 t1 = __half22float2(*(const __half2*)&tb1[nt]);
                s[nt][0] += bb.x + t0.x; s[nt][1] += bb.y + t0.y;
                s[nt][2] += bb.x + t1.x; s[nt][3] += bb.y + t1.y;
                cm0 = fmaxf(cm0, fmaxf(s[nt][0], s[nt][1]));
                cm1 = fmaxf(cm1, fmaxf(s[nt][2], s[nt][3]));
            }
            cm0 = fmaxf(cm0, __shfl_xor_sync(~0u, cm0, 1));
            cm0 = fmaxf(cm0, __shfl_xor_sync(~0u, cm0, 2));
            cm1 = fmaxf(cm1, __shfl_xor_sync(~0u, cm1, 1));
            cm1 = fmaxf(cm1, __shfl_xor_sync(~0u, cm1, 2));

            // ---- online rescale ----
            float Mn0 = fmaxf(M0, cm0), Mn1 = fmaxf(M1, cm1);
            float al0 = fexp2(M0 - Mn0), al1 = fexp2(M1 - Mn1);
            M0 = Mn0; M1 = Mn1;
            #pragma unroll
            for (int ct = 0; ct < 5; ct++) {
                O[ct][0] *= al0; O[ct][1] *= al0;
                O[ct][2] *= al1; O[ct][3] *= al1;
            }

            // ---- exp2 in f16x2: output IS the P A-fragment ----
            uint32_t e[6][2];
            #pragma unroll
            for (int nt = 0; nt < 6; nt++) {
                e[nt][0] = hexp2x2(h2u(__floats2half2_rn(s[nt][0] - M0, s[nt][1] - M0)));
                e[nt][1] = hexp2x2(h2u(__floats2half2_rn(s[nt][2] - M1, s[nt][3] - M1)));
            }

            // ---- AV + ones-column sum ----
            #pragma unroll
            for (int j = 0; j < 3; j++) {       // k16 steps
                uint32_t pa[4] = { e[2 * j][0], e[2 * j][1],
                                   e[2 * j + 1][0], e[2 * j + 1][1] };
                #pragma unroll
                for (int ct2 = 0; ct2 < 2; ct2++) {
                    uint32_t vb[4];
                    ldm_x4t(vb, &Vs[(k0c + j * 16 + (lane & 15)) * KSS
                                    + ct2 * 16 + (lane >> 4) * 8]);
                    mma16(O[ct2 * 2 + 0], pa, &vb[0]);
                    mma16(O[ct2 * 2 + 1], pa, &vb[2]);
                }
                mma16(O[4], pa, onesb);         // row sums
            }

            #pragma unroll
            for (int nt = 0; nt < 6; nt++) { tb0[nt] = tn0[nt]; tb1[nt] = tn1[nt]; }
        }

        // ---- normalize, gate, store og ----
        float inv0 = 1.0f / O[4][0], inv1 = 1.0f / O[4][2];
        #pragma unroll
        for (int ct = 0; ct < 4; ct++) {
            int c = ct * 8 + 2 * t;
            size_t idx0 = (size_t)(i * NSEQ + q0 + g) * CIN + h * CHD + c;
            size_t idx1 = idx0 + (size_t)8 * CIN;
            float2 gg0 = __half22float2(*(const __half2*)&g_gh[idx0]);
            float2 gg1 = __half22float2(*(const __half2*)&g_gh[idx1]);
            *(uint32_t*)&g_ogh[idx0] = h2u(__floats2half2_rn(
                O[ct][0] * inv0 * gg0.x, O[ct][1] * inv0 * gg0.y));
            *(uint32_t*)&g_ogh[idx1] = h2u(__floats2half2_rn(
                O[ct][2] * inv1 * gg1.x, O[ct][3] * inv1 * gg1.y));
        }
    }
}

// ============================================================
// Kernel 3: out = og @ wo, fp16 mma. og already half.
// ============================================================
__global__ __launch_bounds__(256, 2)
void out_tc(const float* __restrict__ wo, float* __restrict__ out) {
    extern __shared__ __half smh[];
    __half* As = smh;
    __half* Bs = smh + 128 * HS;
    int tid = threadIdx.x, lane = tid & 31, warp = tid >> 5;
    int g = lane >> 2, t = lane & 3;
    int m0 = blockIdx.x * 128;

    #pragma unroll
    for (int e = 0; e < 8; e++) {
        int f = tid + e * 256;
        int row = f >> 4, c8 = (f & 15) * 8;
        *(uint4*)&As[row * HS + c8] = *(const uint4*)&g_ogh[(size_t)(m0 + row) * CIN + c8];
    }
    #pragma unroll
    for (int e = 0; e < 16; e++) {
        int f = tid + e * 256;
        int row = f >> 5, c4 = (f & 31) * 4;
        float4 vb = *(const float4*)&wo[(size_t)row * CIN + c4];
        uint2 ub = { h2u(__floats2half2_rn(vb.x, vb.y)), h2u(__floats2half2_rn(vb.z, vb.w)) };
        *(uint2*)&Bs[row * HS + c4] = ub;
    }
    __syncthreads();

    int wm = warp >> 1, wn = warp & 1;
    float acc[2][8][4] = {};
    #pragma unroll
    for (int kc2 = 0; kc2 < 4; kc2++) {
        uint32_t bf[8][4];
        #pragma unroll
        for (int nt = 0; nt < 8; nt++)
            ldm_x4t(bf[nt], &Bs[(kc2 * 32 + lane) * HS + wn * 64 + nt * 8]);
        #pragma unroll
        for (int kk = 0; kk < 2; kk++) {
            uint32_t af[2][4];
            #pragma unroll
            for (int mt = 0; mt < 2; mt++)
                ldm_x4(af[mt], &As[(wm * 32 + mt * 16 + (lane & 15)) * HS
                                   + (kc2 * 2 + kk) * 16 + (lane >> 4) * 8]);
            #pragma unroll
            for (int nt = 0; nt < 8; nt++) {
                mma16(acc[0][nt], af[0], &bf[nt][kk * 2]);
                mma16(acc[1][nt], af[1], &bf[nt][kk * 2]);
            }
        }
    }
    #pragma unroll
    for (int mt = 0; mt < 2; mt++)
        #pragma unroll
        for (int nt = 0; nt < 8; nt++)
            #pragma unroll
            for (int hf = 0; hf < 2; hf++) {
                int gm  = m0 + wm * 32 + mt * 16 + g + hf * 8;
                int col = wn * 64 + nt * 8 + 2 * t;
                float2 o = { acc[mt][nt][hf * 2 + 0], acc[mt][nt][hf * 2 + 1] };
                *(float2*)&out[(size_t)gm * CIN + col] = o;
            }
}

// ============================================================
extern "C" void kernel_launch(void* const* d_in, const int* in_sizes, int n_in,
                              void* d_out, int out_size) {
    const float* z     = (const float*)d_in[0];
    const float* mask  = (const float*)d_in[1];
    const float* ln_w  = (const float*)d_in[2];
    const float* ln_b  = (const float*)d_in[3];
    const float* w_tri = (const float*)d_in[4];
    const float* wq    = (const float*)d_in[5];
    const float* wk    = (const float*)d_in[6];
    const float* wv    = (const float*)d_in[7];
    const float* wg    = (const float*)d_in[8];
    const float* wo    = (const float*)d_in[9];
    float* out = (float*)d_out;

    size_t proj_smem = (size_t)(3 * 128 * HS) * sizeof(__half);  // 104448
    cudaFuncSetAttribute(proj_tc, cudaFuncAttributeMaxDynamicSharedMemorySize, (int)proj_smem);
    proj_tc<<<NTOK / 128, 256, proj_smem>>>(z, ln_w, ln_b, w_tri, wq, wk, wv, wg);

    size_t att_smem = (size_t)(2 * NSEQ * KSS) * sizeof(__half) + NSEQ * sizeof(float); // 62976
    cudaFuncSetAttribute(attn_tc, cudaFuncAttributeMaxDynamicSharedMemorySize, (int)att_smem);
    dim3 ga(NSEQ, NH);
    attn_tc<<<ga, 256, att_smem>>>(mask);

    size_t out_smem = (size_t)(2 * 128 * HS) * sizeof(__half);   // 69632
    cudaFuncSetAttribute(out_tc, cudaFuncAttributeMaxDynamicSharedMemorySize, (int)out_smem);
    out_tc<<<NTOK / 128, 256, out_smem>>>(wo, out);
}

// round 12
// speedup vs baseline: 1.1464x; 1.0840x over previous
#include <cuda_runtime.h>
#include <cuda_fp16.h>
#include <math.h>
#include <stdint.h>

constexpr int NSEQ = 384;
constexpr int CIN  = 128;
constexpr int NH   = 4;
constexpr int CHD  = 32;
constexpr int NTOK = NSEQ * NSEQ;
constexpr float QSCALE = 0.17677669529663687f;  // 1/sqrt(32)
constexpr float LOG2E  = 1.4426950408889634f;

// ---- scratch ----
__device__ __half g_qh [NTOK * CIN];   // pre-scaled by QSCALE*LOG2E
__device__ __half g_kh [NTOK * CIN];
__device__ __half g_vh [NTOK * CIN];
__device__ __half g_gh [NTOK * CIN];
__device__ __half g_ogh[NTOK * CIN];
__device__ __half g_trih[NH * NTOK];   // [h][q*NSEQ+k], pre-scaled by LOG2E

__device__ __forceinline__ uint32_t h2u(__half2 h) { return *(uint32_t*)&h; }
__device__ __forceinline__ float fexp2(float x) {
    float r; asm("ex2.approx.f32 %0, %1;" : "=f"(r) : "f"(x)); return r;
}
__device__ __forceinline__ uint32_t hexp2x2(uint32_t x) {
    uint32_t r; asm("ex2.approx.f16x2 %0, %1;" : "=r"(r) : "r"(x)); return r;
}

__device__ __forceinline__ void ldm_x4(uint32_t* r, const void* p) {
    uint32_t a = (uint32_t)__cvta_generic_to_shared(p);
    asm volatile("ldmatrix.sync.aligned.m8n8.x4.shared.b16 {%0,%1,%2,%3}, [%4];"
        : "=r"(r[0]), "=r"(r[1]), "=r"(r[2]), "=r"(r[3]) : "r"(a));
}
__device__ __forceinline__ void ldm_x4t(uint32_t* r, const void* p) {
    uint32_t a = (uint32_t)__cvta_generic_to_shared(p);
    asm volatile("ldmatrix.sync.aligned.m8n8.x4.trans.shared.b16 {%0,%1,%2,%3}, [%4];"
        : "=r"(r[0]), "=r"(r[1]), "=r"(r[2]), "=r"(r[3]) : "r"(a));
}
// D += A(16x16) * B(16x8), fp16 in, fp32 accum
__device__ __forceinline__ void mma16(float* d, const uint32_t* a, const uint32_t* b) {
    asm volatile(
        "mma.sync.aligned.m16n8k16.row.col.f32.f16.f16.f32 "
        "{%0,%1,%2,%3},{%4,%5,%6,%7},{%8,%9},{%0,%1,%2,%3};"
        : "+f"(d[0]), "+f"(d[1]), "+f"(d[2]), "+f"(d[3])
        : "r"(a[0]), "r"(a[1]), "r"(a[2]), "r"(a[3]), "r"(b[0]), "r"(b[1]));
}

// ============================================================
// Kernel 1: fused LN + tri + 4-way projections.
// LN: batched warp reduction (all 16 rows' shuffles pipelined).
// tri: computed by the tensor core from the As tile (w_tri
// padded to a 16-col half tile).
// ============================================================
constexpr int HS  = 136;  // halves per smem row (A/B tiles)
constexpr int WTS = 24;   // halves per w_tri smem row

__global__ __launch_bounds__(256, 2)
void proj_tc(const float* __restrict__ z,
             const float* __restrict__ ln_w,
             const float* __restrict__ ln_b,
             const float* __restrict__ w_tri,
             const float* __restrict__ wq, const float* __restrict__ wk,
             const float* __restrict__ wv, const float* __restrict__ wg) {
    extern __shared__ __half smh[];
    __half* As = smh;                         // 128 x HS
    __half* Bbuf[2] = { smh + 128 * HS, smh + 2 * 128 * HS };
    __half* Wt = smh + 3 * 128 * HS;          // 128 x WTS (w_tri padded)
    int tid = threadIdx.x, lane = tid & 31, warp = tid >> 5;
    int g = lane >> 2, t = lane & 3;
    int m0 = blockIdx.x * 128;
    const float* Ws[4] = { wq, wk, wv, wg };

    // ---- LN pass A: partial sums for 16 rows, batched shuffles ----
    float s1[16], s2[16];
    #pragma unroll
    for (int r = 0; r < 16; r++) {
        float4 x = *(const float4*)&z[(size_t)(m0 + warp * 16 + r) * CIN + lane * 4];
        s1[r] = x.x + x.y + x.z + x.w;
        s2[r] = x.x * x.x + x.y * x.y + x.z * x.z + x.w * x.w;
    }
    #pragma unroll
    for (int off = 16; off; off >>= 1)
        #pragma unroll
        for (int r = 0; r < 16; r++) {
            s1[r] += __shfl_xor_sync(~0u, s1[r], off);
            s2[r] += __shfl_xor_sync(~0u, s2[r], off);
        }

    // ---- LN pass B: normalize (z re-read hits L1), write As ----
    {
        float4 w4 = *(const float4*)&ln_w[lane * 4];
        float4 b4 = *(const float4*)&ln_b[lane * 4];
        #pragma unroll
        for (int r = 0; r < 16; r++) {
            int row = warp * 16 + r;
            float mean = s1[r] * (1.0f / CIN);
            float var  = s2[r] * (1.0f / CIN) - mean * mean;
            float rs   = rsqrtf(var + 1e-5f);
            float4 x = *(const float4*)&z[(size_t)(m0 + row) * CIN + lane * 4];
            float zn0 = (x.x - mean) * rs * w4.x + b4.x;
            float zn1 = (x.y - mean) * rs * w4.y + b4.y;
            float zn2 = (x.z - mean) * rs * w4.z + b4.z;
            float zn3 = (x.w - mean) * rs * w4.w + b4.w;
            uint2 u = { h2u(__floats2half2_rn(zn0, zn1)), h2u(__floats2half2_rn(zn2, zn3)) };
            *(uint2*)&As[row * HS + lane * 4] = u;
        }
    }

    // ---- w_tri tile (128 x 16 halves, cols 4..15 zero) ----
    if (tid < 128) {
        float4 v = *(const float4*)&w_tri[tid * NH];
        *(uint2*)&Wt[tid * WTS] = uint2{ h2u(__floats2half2_rn(v.x, v.y)),
                                         h2u(__floats2half2_rn(v.z, v.w)) };
        *(uint2*)&Wt[tid * WTS + 4]  = uint2{ 0u, 0u };
        *(uint2*)&Wt[tid * WTS + 8]  = uint2{ 0u, 0u };
        *(uint2*)&Wt[tid * WTS + 12] = uint2{ 0u, 0u };
    }

    // ---- B0: wq ----
    #pragma unroll
    for (int e = 0; e < 16; e++) {
        int f = tid + e * 256;
        int row = f >> 5, c4 = (f & 31) * 4;
        float4 v = *(const float4*)&wq[(size_t)row * CIN + c4];
        uint2 u = { h2u(__floats2half2_rn(v.x, v.y)), h2u(__floats2half2_rn(v.z, v.w)) };
        *(uint2*)&Bbuf[0][row * HS + c4] = u;
    }
    __syncthreads();

    // ---- tri via mma: warp handles rows warp*16..+15, N=8 (cols 4..7 pad) ----
    {
        float ta[4] = {};
        #pragma unroll
        for (int kc2 = 0; kc2 < 4; kc2++) {
            uint32_t bf[4];
            ldm_x4t(bf, &Wt[(kc2 * 32 + lane) * WTS]);
            #pragma unroll
            for (int kk = 0; kk < 2; kk++) {
                uint32_t af[4];
                ldm_x4(af, &As[(warp * 16 + (lane & 15)) * HS
                               + (kc2 * 2 + kk) * 16 + (lane >> 4) * 8]);
                mma16(ta, af, &bf[kk * 2]);
            }
        }
        if (t < 2) {
            int r0 = m0 + warp * 16 + g;
            g_trih[(size_t)(2 * t)     * NTOK + r0]     = __float2half(ta[0] * LOG2E);
            g_trih[(size_t)(2 * t + 1) * NTOK + r0]     = __float2half(ta[1] * LOG2E);
            g_trih[(size_t)(2 * t)     * NTOK + r0 + 8] = __float2half(ta[2] * LOG2E);
            g_trih[(size_t)(2 * t + 1) * NTOK + r0 + 8] = __float2half(ta[3] * LOG2E);
        }
    }

    int wm = warp >> 1, wn = warp & 1;   // 4x2, warp tile 32m x 64n
    const float QS2 = QSCALE * LOG2E;

    for (int sel = 0; sel < 4; sel++) {
        __half* Bs = Bbuf[sel & 1];
        __half* Bn = Bbuf[(sel + 1) & 1];

        if (sel < 3) {
            const float* W = Ws[sel + 1];
            #pragma unroll
            for (int e = 0; e < 16; e++) {
                int f = tid + e * 256;
                int row = f >> 5, c4 = (f & 31) * 4;
                float4 v = *(const float4*)&W[(size_t)row * CIN + c4];
                uint2 u = { h2u(__floats2half2_rn(v.x, v.y)), h2u(__floats2half2_rn(v.z, v.w)) };
                *(uint2*)&Bn[row * HS + c4] = u;
            }
        }

        float acc[2][8][4] = {};
        #pragma unroll
        for (int kc2 = 0; kc2 < 4; kc2++) {
            uint32_t bf[8][4];
            #pragma unroll
            for (int nt = 0; nt < 8; nt++)
                ldm_x4t(bf[nt], &Bs[(kc2 * 32 + lane) * HS + wn * 64 + nt * 8]);
            #pragma unroll
            for (int kk = 0; kk < 2; kk++) {
                uint32_t af[2][4];
                #pragma unroll
                for (int mt = 0; mt < 2; mt++)
                    ldm_x4(af[mt], &As[(wm * 32 + mt * 16 + (lane & 15)) * HS
                                       + (kc2 * 2 + kk) * 16 + (lane >> 4) * 8]);
                #pragma unroll
                for (int nt = 0; nt < 8; nt++) {
                    mma16(acc[0][nt], af[0], &bf[nt][kk * 2]);
                    mma16(acc[1][nt], af[1], &bf[nt][kk * 2]);
                }
            }
        }

        #pragma unroll
        for (int mt = 0; mt < 2; mt++)
            #pragma unroll
            for (int nt = 0; nt < 8; nt++)
                #pragma unroll
                for (int hf = 0; hf < 2; hf++) {
                    int gm  = m0 + wm * 32 + mt * 16 + g + hf * 8;
                    int col = wn * 64 + nt * 8 + 2 * t;
                    float c0 = acc[mt][nt][hf * 2 + 0], c1 = acc[mt][nt][hf * 2 + 1];
                    size_t idx = (size_t)gm * CIN + col;
                    if (sel == 0)
                        *(uint32_t*)&g_qh[idx] = h2u(__floats2half2_rn(c0 * QS2, c1 * QS2));
                    else if (sel == 1)
                        *(uint32_t*)&g_kh[idx] = h2u(__floats2half2_rn(c0, c1));
                    else if (sel == 2)
                        *(uint32_t*)&g_vh[idx] = h2u(__floats2half2_rn(c0, c1));
                    else
                        *(uint32_t*)&g_gh[idx] = h2u(__floats2half2_rn(
                            1.0f / (1.0f + __expf(-c0)), 1.0f / (1.0f + __expf(-c1))));
                }
        __syncthreads();
    }
}

// ============================================================
// Kernel 2: attention (unchanged from R11).
// ============================================================
constexpr int KSS = 40;   // halves per K/V row

__global__ __launch_bounds__(256, 2)
void attn_tc(const float* __restrict__ mask) {
    int i = blockIdx.x, h = blockIdx.y;
    extern __shared__ __half smh[];
    __half* Ks  = smh;                  // 384 x 40
    __half* Vs  = smh + NSEQ * KSS;     // 384 x 40
    float*  bsm = (float*)(smh + 2 * NSEQ * KSS);  // 384

    int tid = threadIdx.x, lane = tid & 31, warp = tid >> 5;
    int g = lane >> 2, t = lane & 3;

    const __half* gK = g_kh + (size_t)(i * NSEQ) * CIN + h * CHD;
    const __half* gV = g_vh + (size_t)(i * NSEQ) * CIN + h * CHD;
    #pragma unroll
    for (int e = 0; e < 12; e++) {
        int f = tid + e * 256;              // 3072 4-half units
        int row = f >> 3, c4 = (f & 7) * 4;
        *(uint2*)&Ks[row * KSS + c4] = *(const uint2*)&gK[(size_t)row * CIN + c4];
        *(uint2*)&Vs[row * KSS + c4] = *(const uint2*)&gV[(size_t)row * CIN + c4];
    }
    {
        int k = tid;
        if (k < NSEQ) bsm[k] = LOG2E * 1e9f * (mask[i * NSEQ + k] - 1.0f);
        k += 256;
        if (k < NSEQ) bsm[k] = LOG2E * 1e9f * (mask[i * NSEQ + k] - 1.0f);
    }
    __syncthreads();

    const __half* trih = g_trih + (size_t)h * NTOK;
    const uint32_t onesb[2] = { 0x3C003C00u, 0x3C003C00u };   // fp16 1.0 x2

    for (int tile = warp; tile < 24; tile += 8) {
        int q0 = tile * 16;
        int qa = q0 + g, qb = qa + 8;
        const __half* triA = trih + (size_t)qa * NSEQ;
        const __half* triB = trih + (size_t)qb * NSEQ;

        const __half* gQ = g_qh + (size_t)(i * NSEQ + q0) * CIN + h * CHD;
        uint32_t qa_[2][4];
        #pragma unroll
        for (int kc = 0; kc < 2; kc++) {
            qa_[kc][0] = *(const uint32_t*)&gQ[(size_t)g * CIN + kc * 16 + 2 * t];
            qa_[kc][1] = *(const uint32_t*)&gQ[(size_t)(g + 8) * CIN + kc * 16 + 2 * t];
            qa_[kc][2] = *(const uint32_t*)&gQ[(size_t)g * CIN + kc * 16 + 2 * t + 8];
            qa_[kc][3] = *(const uint32_t*)&gQ[(size_t)(g + 8) * CIN + kc * 16 + 2 * t + 8];
        }

        float M0 = -1e30f, M1 = -1e30f;
        float O[5][4] = {};    // O[4] = row-sum column (P @ ones)

        uint32_t tb0[6], tb1[6];
        #pragma unroll
        for (int nt = 0; nt < 6; nt++) {
            int k = nt * 8 + 2 * t;
            tb0[nt] = *(const uint32_t*)&triA[k];
            tb1[nt] = *(const uint32_t*)&triB[k];
        }

        #pragma unroll
        for (int ch = 0; ch < 8; ch++) {      // 48-k chunks
            int k0c = ch * 48;

            float s[6][4];
            #pragma unroll
            for (int nt = 0; nt < 6; nt++) {
                s[nt][0] = s[nt][1] = s[nt][2] = s[nt][3] = 0.f;
                uint32_t bf[4];
                ldm_x4(bf, &Ks[(k0c + nt * 8 + (lane & 7)) * KSS + (lane >> 3) * 8]);
                mma16(s[nt], qa_[0], &bf[0]);
                mma16(s[nt], qa_[1], &bf[2]);
            }

            uint32_t tn0[6], tn1[6];
            if (ch < 7) {
                #pragma unroll
                for (int nt = 0; nt < 6; nt++) {
                    int k = k0c + 48 + nt * 8 + 2 * t;
                    tn0[nt] = *(const uint32_t*)&triA[k];
                    tn1[nt] = *(const uint32_t*)&triB[k];
                }
            }

            float cm0 = -1e30f, cm1 = -1e30f;
            #pragma unroll
            for (int nt = 0; nt < 6; nt++) {
                int k = k0c + nt * 8 + 2 * t;
                float2 bb = *(const float2*)&bsm[k];
                float2 t0 = __half22float2(*(const __half2*)&tb0[nt]);
                float2 t1 = __half22float2(*(const __half2*)&tb1[nt]);
                s[nt][0] += bb.x + t0.x; s[nt][1] += bb.y + t0.y;
                s[nt][2] += bb.x + t1.x; s[nt][3] += bb.y + t1.y;
                cm0 = fmaxf(cm0, fmaxf(s[nt][0], s[nt][1]));
                cm1 = fmaxf(cm1, fmaxf(s[nt][2], s[nt][3]));
            }
            cm0 = fmaxf(cm0, __shfl_xor_sync(~0u, cm0, 1));
            cm0 = fmaxf(cm0, __shfl_xor_sync(~0u, cm0, 2));
            cm1 = fmaxf(cm1, __shfl_xor_sync(~0u, cm1, 1));
            cm1 = fmaxf(cm1, __shfl_xor_sync(~0u, cm1, 2));

            float Mn0 = fmaxf(M0, cm0), Mn1 = fmaxf(M1, cm1);
            float al0 = fexp2(M0 - Mn0), al1 = fexp2(M1 - Mn1);
            M0 = Mn0; M1 = Mn1;
            #pragma unroll
            for (int ct = 0; ct < 5; ct++) {
                O[ct][0] *= al0; O[ct][1] *= al0;
                O[ct][2] *= al1; O[ct][3] *= al1;
            }

            uint32_t e[6][2];
            #pragma unroll
            for (int nt = 0; nt < 6; nt++) {
                e[nt][0] = hexp2x2(h2u(__floats2half2_rn(s[nt][0] - M0, s[nt][1] - M0)));
                e[nt][1] = hexp2x2(h2u(__floats2half2_rn(s[nt][2] - M1, s[nt][3] - M1)));
            }

            #pragma unroll
            for (int j = 0; j < 3; j++) {       // k16 steps
                uint32_t pa[4] = { e[2 * j][0], e[2 * j][1],
                                   e[2 * j + 1][0], e[2 * j + 1][1] };
                #pragma unroll
                for (int ct2 = 0; ct2 < 2; ct2++) {
                    uint32_t vb[4];
                    ldm_x4t(vb, &Vs[(k0c + j * 16 + (lane & 15)) * KSS
                                    + ct2 * 16 + (lane >> 4) * 8]);
                    mma16(O[ct2 * 2 + 0], pa, &vb[0]);
                    mma16(O[ct2 * 2 + 1], pa, &vb[2]);
                }
                mma16(O[4], pa, onesb);         // row sums
            }

            #pragma unroll
            for (int nt = 0; nt < 6; nt++) { tb0[nt] = tn0[nt]; tb1[nt] = tn1[nt]; }
        }

        float inv0 = 1.0f / O[4][0], inv1 = 1.0f / O[4][2];
        #pragma unroll
        for (int ct = 0; ct < 4; ct++) {
            int c = ct * 8 + 2 * t;
            size_t idx0 = (size_t)(i * NSEQ + q0 + g) * CIN + h * CHD + c;
            size_t idx1 = idx0 + (size_t)8 * CIN;
            float2 gg0 = __half22float2(*(const __half2*)&g_gh[idx0]);
            float2 gg1 = __half22float2(*(const __half2*)&g_gh[idx1]);
            *(uint32_t*)&g_ogh[idx0] = h2u(__floats2half2_rn(
                O[ct][0] * inv0 * gg0.x, O[ct][1] * inv0 * gg0.y));
            *(uint32_t*)&g_ogh[idx1] = h2u(__floats2half2_rn(
                O[ct][2] * inv1 * gg1.x, O[ct][3] * inv1 * gg1.y));
        }
    }
}

// ============================================================
// Kernel 3: out = og @ wo, fp16 mma (unchanged).
// ============================================================
__global__ __launch_bounds__(256, 2)
void out_tc(const float* __restrict__ wo, float* __restrict__ out) {
    extern __shared__ __half smh[];
    __half* As = smh;
    __half* Bs = smh + 128 * HS;
    int tid = threadIdx.x, lane = tid & 31, warp = tid >> 5;
    int g = lane >> 2, t = lane & 3;
    int m0 = blockIdx.x * 128;

    #pragma unroll
    for (int e = 0; e < 8; e++) {
        int f = tid + e * 256;
        int row = f >> 4, c8 = (f & 15) * 8;
        *(uint4*)&As[row * HS + c8] = *(const uint4*)&g_ogh[(size_t)(m0 + row) * CIN + c8];
    }
    #pragma unroll
    for (int e = 0; e < 16; e++) {
        int f = tid + e * 256;
        int row = f >> 5, c4 = (f & 31) * 4;
        float4 vb = *(const float4*)&wo[(size_t)row * CIN + c4];
        uint2 ub = { h2u(__floats2half2_rn(vb.x, vb.y)), h2u(__floats2half2_rn(vb.z, vb.w)) };
        *(uint2*)&Bs[row * HS + c4] = ub;
    }
    __syncthreads();

    int wm = warp >> 1, wn = warp & 1;
    float acc[2][8][4] = {};
    #pragma unroll
    for (int kc2 = 0; kc2 < 4; kc2++) {
        uint32_t bf[8][4];
        #pragma unroll
        for (int nt = 0; nt < 8; nt++)
            ldm_x4t(bf[nt], &Bs[(kc2 * 32 + lane) * HS + wn * 64 + nt * 8]);
        #pragma unroll
        for (int kk = 0; kk < 2; kk++) {
            uint32_t af[2][4];
            #pragma unroll
            for (int mt = 0; mt < 2; mt++)
                ldm_x4(af[mt], &As[(wm * 32 + mt * 16 + (lane & 15)) * HS
                                   + (kc2 * 2 + kk) * 16 + (lane >> 4) * 8]);
            #pragma unroll
            for (int nt = 0; nt < 8; nt++) {
                mma16(acc[0][nt], af[0], &bf[nt][kk * 2]);
                mma16(acc[1][nt], af[1], &bf[nt][kk * 2]);
            }
        }
    }
    #pragma unroll
    for (int mt = 0; mt < 2; mt++)
        #pragma unroll
        for (int nt = 0; nt < 8; nt++)
            #pragma unroll
            for (int hf = 0; hf < 2; hf++) {
                int gm  = m0 + wm * 32 + mt * 16 + g + hf * 8;
                int col = wn * 64 + nt * 8 + 2 * t;
                float2 o = { acc[mt][nt][hf * 2 + 0], acc[mt][nt][hf * 2 + 1] };
                *(float2*)&out[(size_t)gm * CIN + col] = o;
            }
}

// ============================================================
extern "C" void kernel_launch(void* const* d_in, const int* in_sizes, int n_in,
                              void* d_out, int out_size) {
    const float* z     = (const float*)d_in[0];
    const float* mask  = (const float*)d_in[1];
    const float* ln_w  = (const float*)d_in[2];
    const float* ln_b  = (const float*)d_in[3];
    const float* w_tri = (const float*)d_in[4];
    const float* wq    = (const float*)d_in[5];
    const float* wk    = (const float*)d_in[6];
    const float* wv    = (const float*)d_in[7];
    const float* wg    = (const float*)d_in[8];
    const float* wo    = (const float*)d_in[9];
    float* out = (float*)d_out;

    size_t proj_smem = (size_t)(3 * 128 * HS + 128 * WTS) * sizeof(__half);  // 110592
    cudaFuncSetAttribute(proj_tc, cudaFuncAttributeMaxDynamicSharedMemorySize, (int)proj_smem);
    proj_tc<<<NTOK / 128, 256, proj_smem>>>(z, ln_w, ln_b, w_tri, wq, wk, wv, wg);

    size_t att_smem = (size_t)(2 * NSEQ * KSS) * sizeof(__half) + NSEQ * sizeof(float); // 62976
    cudaFuncSetAttribute(attn_tc, cudaFuncAttributeMaxDynamicSharedMemorySize, (int)att_smem);
    dim3 ga(NSEQ, NH);
    attn_tc<<<ga, 256, att_smem>>>(mask);

    size_t out_smem = (size_t)(2 * 128 * HS) * sizeof(__half);   // 69632
    cudaFuncSetAttribute(out_tc, cudaFuncAttributeMaxDynamicSharedMemorySize, (int)out_smem);
    out_tc<<<NTOK / 128, 256, out_smem>>>(wo, out);
}

// round 14
// speedup vs baseline: 1.1501x; 1.0033x over previous
#include <cuda_runtime.h>
#include <cuda_fp16.h>
#include <math.h>
#include <stdint.h>

constexpr int NSEQ = 384;
constexpr int CIN  = 128;
constexpr int NH   = 4;
constexpr int CHD  = 32;
constexpr int NTOK = NSEQ * NSEQ;
constexpr float QSCALE = 0.17677669529663687f;  // 1/sqrt(32)
constexpr float LOG2E  = 1.4426950408889634f;

// ---- scratch ----
__device__ __half g_qh [NTOK * CIN];   // pre-scaled by QSCALE*LOG2E
__device__ __half g_kh [NTOK * CIN];
__device__ __half g_vh [NTOK * CIN];
__device__ __half g_gh [NTOK * CIN];
__device__ __half g_ogh[NTOK * CIN];
__device__ __half g_trih[NH * NTOK];   // [h][q*NSEQ+k], pre-scaled by LOG2E

__device__ __forceinline__ uint32_t h2u(__half2 h) { return *(uint32_t*)&h; }
__device__ __forceinline__ float fexp2(float x) {
    float r; asm("ex2.approx.f32 %0, %1;" : "=f"(r) : "f"(x)); return r;
}
__device__ __forceinline__ uint32_t hexp2x2(uint32_t x) {
    uint32_t r; asm("ex2.approx.f16x2 %0, %1;" : "=r"(r) : "r"(x)); return r;
}

__device__ __forceinline__ void ldm_x4(uint32_t* r, const void* p) {
    uint32_t a = (uint32_t)__cvta_generic_to_shared(p);
    asm volatile("ldmatrix.sync.aligned.m8n8.x4.shared.b16 {%0,%1,%2,%3}, [%4];"
        : "=r"(r[0]), "=r"(r[1]), "=r"(r[2]), "=r"(r[3]) : "r"(a));
}
__device__ __forceinline__ void ldm_x4t(uint32_t* r, const void* p) {
    uint32_t a = (uint32_t)__cvta_generic_to_shared(p);
    asm volatile("ldmatrix.sync.aligned.m8n8.x4.trans.shared.b16 {%0,%1,%2,%3}, [%4];"
        : "=r"(r[0]), "=r"(r[1]), "=r"(r[2]), "=r"(r[3]) : "r"(a));
}
// D += A(16x16) * B(16x8), fp16 in, fp32 accum
__device__ __forceinline__ void mma16(float* d, const uint32_t* a, const uint32_t* b) {
    asm volatile(
        "mma.sync.aligned.m16n8k16.row.col.f32.f16.f16.f32 "
        "{%0,%1,%2,%3},{%4,%5,%6,%7},{%8,%9},{%0,%1,%2,%3};"
        : "+f"(d[0]), "+f"(d[1]), "+f"(d[2]), "+f"(d[3])
        : "r"(a[0]), "r"(a[1]), "r"(a[2]), "r"(a[3]), "r"(b[0]), "r"(b[1]));
}

// ============================================================
// Kernel 1: fused LN + tri + 4-way projections.
// LN: batched warp reduction (all 16 rows' shuffles pipelined).
// tri: computed by the tensor core from the As tile.
// ============================================================
constexpr int HS  = 136;  // halves per smem row (A/B tiles)
constexpr int WTS = 24;   // halves per w_tri smem row

__global__ __launch_bounds__(256, 2)
void proj_tc(const float* __restrict__ z,
             const float* __restrict__ ln_w,
             const float* __restrict__ ln_b,
             const float* __restrict__ w_tri,
             const float* __restrict__ wq, const float* __restrict__ wk,
             const float* __restrict__ wv, const float* __restrict__ wg) {
    extern __shared__ __half smh[];
    __half* As = smh;                         // 128 x HS
    __half* Bbuf[2] = { smh + 128 * HS, smh + 2 * 128 * HS };
    __half* Wt = smh + 3 * 128 * HS;          // 128 x WTS (w_tri padded)
    int tid = threadIdx.x, lane = tid & 31, warp = tid >> 5;
    int g = lane >> 2, t = lane & 3;
    int m0 = blockIdx.x * 128;
    const float* Ws[4] = { wq, wk, wv, wg };

    // ---- LN pass A: partial sums for 16 rows, batched shuffles ----
    float s1[16], s2[16];
    #pragma unroll
    for (int r = 0; r < 16; r++) {
        float4 x = *(const float4*)&z[(size_t)(m0 + warp * 16 + r) * CIN + lane * 4];
        s1[r] = x.x + x.y + x.z + x.w;
        s2[r] = x.x * x.x + x.y * x.y + x.z * x.z + x.w * x.w;
    }
    #pragma unroll
    for (int off = 16; off; off >>= 1)
        #pragma unroll
        for (int r = 0; r < 16; r++) {
            s1[r] += __shfl_xor_sync(~0u, s1[r], off);
            s2[r] += __shfl_xor_sync(~0u, s2[r], off);
        }

    // ---- LN pass B: normalize (z re-read hits L1), write As ----
    {
        float4 w4 = *(const float4*)&ln_w[lane * 4];
        float4 b4 = *(const float4*)&ln_b[lane * 4];
        #pragma unroll
        for (int r = 0; r < 16; r++) {
            int row = warp * 16 + r;
            float mean = s1[r] * (1.0f / CIN);
            float var  = s2[r] * (1.0f / CIN) - mean * mean;
            float rs   = rsqrtf(var + 1e-5f);
            float4 x = *(const float4*)&z[(size_t)(m0 + row) * CIN + lane * 4];
            float zn0 = (x.x - mean) * rs * w4.x + b4.x;
            float zn1 = (x.y - mean) * rs * w4.y + b4.y;
            float zn2 = (x.z - mean) * rs * w4.z + b4.z;
            float zn3 = (x.w - mean) * rs * w4.w + b4.w;
            uint2 u = { h2u(__floats2half2_rn(zn0, zn1)), h2u(__floats2half2_rn(zn2, zn3)) };
            *(uint2*)&As[row * HS + lane * 4] = u;
        }
    }

    // ---- w_tri tile (128 x 16 halves, cols 4..15 zero) ----
    if (tid < 128) {
        float4 v = *(const float4*)&w_tri[tid * NH];
        *(uint2*)&Wt[tid * WTS] = uint2{ h2u(__floats2half2_rn(v.x, v.y)),
                                         h2u(__floats2half2_rn(v.z, v.w)) };
        *(uint2*)&Wt[tid * WTS + 4]  = uint2{ 0u, 0u };
        *(uint2*)&Wt[tid * WTS + 8]  = uint2{ 0u, 0u };
        *(uint2*)&Wt[tid * WTS + 12] = uint2{ 0u, 0u };
    }

    // ---- B0: wq ----
    #pragma unroll
    for (int e = 0; e < 16; e++) {
        int f = tid + e * 256;
        int row = f >> 5, c4 = (f & 31) * 4;
        float4 v = *(const float4*)&wq[(size_t)row * CIN + c4];
        uint2 u = { h2u(__floats2half2_rn(v.x, v.y)), h2u(__floats2half2_rn(v.z, v.w)) };
        *(uint2*)&Bbuf[0][row * HS + c4] = u;
    }
    __syncthreads();

    // ---- tri via mma: warp handles rows warp*16..+15 ----
    {
        float ta[4] = {};
        #pragma unroll
        for (int kc2 = 0; kc2 < 4; kc2++) {
            uint32_t bf[4];
            ldm_x4t(bf, &Wt[(kc2 * 32 + lane) * WTS]);
            #pragma unroll
            for (int kk = 0; kk < 2; kk++) {
                uint32_t af[4];
                ldm_x4(af, &As[(warp * 16 + (lane & 15)) * HS
                               + (kc2 * 2 + kk) * 16 + (lane >> 4) * 8]);
                mma16(ta, af, &bf[kk * 2]);
            }
        }
        if (t < 2) {
            int r0 = m0 + warp * 16 + g;
            g_trih[(size_t)(2 * t)     * NTOK + r0]     = __float2half(ta[0] * LOG2E);
            g_trih[(size_t)(2 * t + 1) * NTOK + r0]     = __float2half(ta[1] * LOG2E);
            g_trih[(size_t)(2 * t)     * NTOK + r0 + 8] = __float2half(ta[2] * LOG2E);
            g_trih[(size_t)(2 * t + 1) * NTOK + r0 + 8] = __float2half(ta[3] * LOG2E);
        }
    }

    int wm = warp >> 1, wn = warp & 1;   // 4x2, warp tile 32m x 64n
    const float QS2 = QSCALE * LOG2E;

    for (int sel = 0; sel < 4; sel++) {
        __half* Bs = Bbuf[sel & 1];
        __half* Bn = Bbuf[(sel + 1) & 1];

        if (sel < 3) {
            const float* W = Ws[sel + 1];
            #pragma unroll
            for (int e = 0; e < 16; e++) {
                int f = tid + e * 256;
                int row = f >> 5, c4 = (f & 31) * 4;
                float4 v = *(const float4*)&W[(size_t)row * CIN + c4];
                uint2 u = { h2u(__floats2half2_rn(v.x, v.y)), h2u(__floats2half2_rn(v.z, v.w)) };
                *(uint2*)&Bn[row * HS + c4] = u;
            }
        }

        float acc[2][8][4] = {};
        #pragma unroll
        for (int kc2 = 0; kc2 < 4; kc2++) {
            uint32_t bf[8][4];
            #pragma unroll
            for (int nt = 0; nt < 8; nt++)
                ldm_x4t(bf[nt], &Bs[(kc2 * 32 + lane) * HS + wn * 64 + nt * 8]);
            #pragma unroll
            for (int kk = 0; kk < 2; kk++) {
                uint32_t af[2][4];
                #pragma unroll
                for (int mt = 0; mt < 2; mt++)
                    ldm_x4(af[mt], &As[(wm * 32 + mt * 16 + (lane & 15)) * HS
                                       + (kc2 * 2 + kk) * 16 + (lane >> 4) * 8]);
                #pragma unroll
                for (int nt = 0; nt < 8; nt++) {
                    mma16(acc[0][nt], af[0], &bf[nt][kk * 2]);
                    mma16(acc[1][nt], af[1], &bf[nt][kk * 2]);
                }
            }
        }

        #pragma unroll
        for (int mt = 0; mt < 2; mt++)
            #pragma unroll
            for (int nt = 0; nt < 8; nt++)
                #pragma unroll
                for (int hf = 0; hf < 2; hf++) {
                    int gm  = m0 + wm * 32 + mt * 16 + g + hf * 8;
                    int col = wn * 64 + nt * 8 + 2 * t;
                    float c0 = acc[mt][nt][hf * 2 + 0], c1 = acc[mt][nt][hf * 2 + 1];
                    size_t idx = (size_t)gm * CIN + col;
                    if (sel == 0)
                        *(uint32_t*)&g_qh[idx] = h2u(__floats2half2_rn(c0 * QS2, c1 * QS2));
                    else if (sel == 1)
                        *(uint32_t*)&g_kh[idx] = h2u(__floats2half2_rn(c0, c1));
                    else if (sel == 2)
                        *(uint32_t*)&g_vh[idx] = h2u(__floats2half2_rn(c0, c1));
                    else
                        *(uint32_t*)&g_gh[idx] = h2u(__floats2half2_rn(
                            1.0f / (1.0f + __expf(-c0)), 1.0f / (1.0f + __expf(-c1))));
                }
        __syncthreads();
    }
}

// ============================================================
// Kernel 2: attention. 3 CTAs/SM (6 warps/SMSP): tri prefetch
// registers removed (direct L2 loads), f16x2 exp2 softmax,
// ones-column row sums, 48-k chunks.
// ============================================================
constexpr int KSS = 40;   // halves per K/V row

__global__ __launch_bounds__(256, 3)
void attn_tc(const float* __restrict__ mask) {
    int i = blockIdx.x, h = blockIdx.y;
    extern __shared__ __half smh[];
    __half* Ks  = smh;                  // 384 x 40
    __half* Vs  = smh + NSEQ * KSS;     // 384 x 40
    float*  bsm = (float*)(smh + 2 * NSEQ * KSS);  // 384

    int tid = threadIdx.x, lane = tid & 31, warp = tid >> 5;
    int g = lane >> 2, t = lane & 3;

    const __half* gK = g_kh + (size_t)(i * NSEQ) * CIN + h * CHD;
    const __half* gV = g_vh + (size_t)(i * NSEQ) * CIN + h * CHD;
    #pragma unroll
    for (int e = 0; e < 12; e++) {
        int f = tid + e * 256;              // 3072 4-half units
        int row = f >> 3, c4 = (f & 7) * 4;
        *(uint2*)&Ks[row * KSS + c4] = *(const uint2*)&gK[(size_t)row * CIN + c4];
        *(uint2*)&Vs[row * KSS + c4] = *(const uint2*)&gV[(size_t)row * CIN + c4];
    }
    {
        int k = tid;
        if (k < NSEQ) bsm[k] = LOG2E * 1e9f * (mask[i * NSEQ + k] - 1.0f);
        k += 256;
        if (k < NSEQ) bsm[k] = LOG2E * 1e9f * (mask[i * NSEQ + k] - 1.0f);
    }
    __syncthreads();

    const __half* trih = g_trih + (size_t)h * NTOK;
    const uint32_t onesb[2] = { 0x3C003C00u, 0x3C003C00u };   // fp16 1.0 x2

    for (int tile = warp; tile < 24; tile += 8) {
        int q0 = tile * 16;
        const __half* triA = trih + (size_t)(q0 + g) * NSEQ;
        const __half* triB = triA + (size_t)8 * NSEQ;

        const __half* gQ = g_qh + (size_t)(i * NSEQ + q0) * CIN + h * CHD;
        uint32_t qa_[2][4];
        #pragma unroll
        for (int kc = 0; kc < 2; kc++) {
            qa_[kc][0] = *(const uint32_t*)&gQ[(size_t)g * CIN + kc * 16 + 2 * t];
            qa_[kc][1] = *(const uint32_t*)&gQ[(size_t)(g + 8) * CIN + kc * 16 + 2 * t];
            qa_[kc][2] = *(const uint32_t*)&gQ[(size_t)g * CIN + kc * 16 + 2 * t + 8];
            qa_[kc][3] = *(const uint32_t*)&gQ[(size_t)(g + 8) * CIN + kc * 16 + 2 * t + 8];
        }

        float M0 = -1e30f, M1 = -1e30f;
        float O[5][4] = {};    // O[4] = row-sum column (P @ ones)

        #pragma unroll
        for (int ch = 0; ch < 8; ch++) {      // 48-k chunks
            int k0c = ch * 48;

            // ---- QK scores (log2 domain) ----
            float s[6][4];
            #pragma unroll
            for (int nt = 0; nt < 6; nt++) {
                s[nt][0] = s[nt][1] = s[nt][2] = s[nt][3] = 0.f;
                uint32_t bf[4];
                ldm_x4(bf, &Ks[(k0c + nt * 8 + (lane & 7)) * KSS + (lane >> 3) * 8]);
                mma16(s[nt], qa_[0], &bf[0]);
                mma16(s[nt], qa_[1], &bf[2]);
            }

            // ---- biases (tri direct from L2) + chunk max ----
            float cm0 = -1e30f, cm1 = -1e30f;
            #pragma unroll
            for (int nt = 0; nt < 6; nt++) {
                int k = k0c + nt * 8 + 2 * t;
                float2 bb = *(const float2*)&bsm[k];
                float2 t0 = __half22float2(*(const __half2*)&triA[k]);
                float2 t1 = __half22float2(*(const __half2*)&triB[k]);
                s[nt][0] += bb.x + t0.x; s[nt][1] += bb.y + t0.y;
                s[nt][2] += bb.x + t1.x; s[nt][3] += bb.y + t1.y;
                cm0 = fmaxf(cm0, fmaxf(s[nt][0], s[nt][1]));
                cm1 = fmaxf(cm1, fmaxf(s[nt][2], s[nt][3]));
            }
            cm0 = fmaxf(cm0, __shfl_xor_sync(~0u, cm0, 1));
            cm0 = fmaxf(cm0, __shfl_xor_sync(~0u, cm0, 2));
            cm1 = fmaxf(cm1, __shfl_xor_sync(~0u, cm1, 1));
            cm1 = fmaxf(cm1, __shfl_xor_sync(~0u, cm1, 2));

            // ---- online rescale (O[4] sum column rescales with O) ----
            float Mn0 = fmaxf(M0, cm0), Mn1 = fmaxf(M1, cm1);
            float al0 = fexp2(M0 - Mn0), al1 = fexp2(M1 - Mn1);
            M0 = Mn0; M1 = Mn1;
            #pragma unroll
            for (int ct = 0; ct < 5; ct++) {
                O[ct][0] *= al0; O[ct][1] *= al0;
                O[ct][2] *= al1; O[ct][3] *= al1;
            }

            // ---- exp2 in f16x2: output IS the P A-fragment ----
            uint32_t e[6][2];
            #pragma unroll
            for (int nt = 0; nt < 6; nt++) {
                e[nt][0] = hexp2x2(h2u(__floats2half2_rn(s[nt][0] - M0, s[nt][1] - M0)));
                e[nt][1] = hexp2x2(h2u(__floats2half2_rn(s[nt][2] - M1, s[nt][3] - M1)));
            }

            // ---- AV + ones-column sum ----
            #pragma unroll
            for (int j = 0; j < 3; j++) {       // k16 steps
                uint32_t pa[4] = { e[2 * j][0], e[2 * j][1],
                                   e[2 * j + 1][0], e[2 * j + 1][1] };
                #pragma unroll
                for (int ct2 = 0; ct2 < 2; ct2++) {
                    uint32_t vb[4];
                    ldm_x4t(vb, &Vs[(k0c + j * 16 + (lane & 15)) * KSS
                                    + ct2 * 16 + (lane >> 4) * 8]);
                    mma16(O[ct2 * 2 + 0], pa, &vb[0]);
                    mma16(O[ct2 * 2 + 1], pa, &vb[2]);
                }
                mma16(O[4], pa, onesb);         // row sums
            }
        }

        // ---- normalize (l = ones column), gate, store og ----
        float inv0 = 1.0f / O[4][0], inv1 = 1.0f / O[4][2];
        #pragma unroll
        for (int ct = 0; ct < 4; ct++) {
            int c = ct * 8 + 2 * t;
            size_t idx0 = (size_t)(i * NSEQ + q0 + g) * CIN + h * CHD + c;
            size_t idx1 = idx0 + (size_t)8 * CIN;
            float2 gg0 = __half22float2(*(const __half2*)&g_gh[idx0]);
            float2 gg1 = __half22float2(*(const __half2*)&g_gh[idx1]);
            *(uint32_t*)&g_ogh[idx0] = h2u(__floats2half2_rn(
                O[ct][0] * inv0 * gg0.x, O[ct][1] * inv0 * gg0.y));
            *(uint32_t*)&g_ogh[idx1] = h2u(__floats2half2_rn(
                O[ct][2] * inv1 * gg1.x, O[ct][3] * inv1 * gg1.y));
        }
    }
}

// ============================================================
// Kernel 3: out = og @ wo, fp16 mma. og already half.
// ============================================================
__global__ __launch_bounds__(256, 2)
void out_tc(const float* __restrict__ wo, float* __restrict__ out) {
    extern __shared__ __half smh[];
    __half* As = smh;
    __half* Bs = smh + 128 * HS;
    int tid = threadIdx.x, lane = tid & 31, warp = tid >> 5;
    int g = lane >> 2, t = lane & 3;
    int m0 = blockIdx.x * 128;

    #pragma unroll
    for (int e = 0; e < 8; e++) {
        int f = tid + e * 256;
        int row = f >> 4, c8 = (f & 15) * 8;
        *(uint4*)&As[row * HS + c8] = *(const uint4*)&g_ogh[(size_t)(m0 + row) * CIN + c8];
    }
    #pragma unroll
    for (int e = 0; e < 16; e++) {
        int f = tid + e * 256;
        int row = f >> 5, c4 = (f & 31) * 4;
        float4 vb = *(const float4*)&wo[(size_t)row * CIN + c4];
        uint2 ub = { h2u(__floats2half2_rn(vb.x, vb.y)), h2u(__floats2half2_rn(vb.z, vb.w)) };
        *(uint2*)&Bs[row * HS + c4] = ub;
    }
    __syncthreads();

    int wm = warp >> 1, wn = warp & 1;
    float acc[2][8][4] = {};
    #pragma unroll
    for (int kc2 = 0; kc2 < 4; kc2++) {
        uint32_t bf[8][4];
        #pragma unroll
        for (int nt = 0; nt < 8; nt++)
            ldm_x4t(bf[nt], &Bs[(kc2 * 32 + lane) * HS + wn * 64 + nt * 8]);
        #pragma unroll
        for (int kk = 0; kk < 2; kk++) {
            uint32_t af[2][4];
            #pragma unroll
            for (int mt = 0; mt < 2; mt++)
                ldm_x4(af[mt], &As[(wm * 32 + mt * 16 + (lane & 15)) * HS
                                   + (kc2 * 2 + kk) * 16 + (lane >> 4) * 8]);
            #pragma unroll
            for (int nt = 0; nt < 8; nt++) {
                mma16(acc[0][nt], af[0], &bf[nt][kk * 2]);
                mma16(acc[1][nt], af[1], &bf[nt][kk * 2]);
            }
        }
    }
    #pragma unroll
    for (int mt = 0; mt < 2; mt++)
        #pragma unroll
        for (int nt = 0; nt < 8; nt++)
            #pragma unroll
            for (int hf = 0; hf < 2; hf++) {
                int gm  = m0 + wm * 32 + mt * 16 + g + hf * 8;
                int col = wn * 64 + nt * 8 + 2 * t;
                float2 o = { acc[mt][nt][hf * 2 + 0], acc[mt][nt][hf * 2 + 1] };
                *(float2*)&out[(size_t)gm * CIN + col] = o;
            }
}

// ============================================================
extern "C" void kernel_launch(void* const* d_in, const int* in_sizes, int n_in,
                              void* d_out, int out_size) {
    const float* z     = (const float*)d_in[0];
    const float* mask  = (const float*)d_in[1];
    const float* ln_w  = (const float*)d_in[2];
    const float* ln_b  = (const float*)d_in[3];
    const float* w_tri = (const float*)d_in[4];
    const float* wq    = (const float*)d_in[5];
    const float* wk    = (const float*)d_in[6];
    const float* wv    = (const float*)d_in[7];
    const float* wg    = (const float*)d_in[8];
    const float* wo    = (const float*)d_in[9];
    float* out = (float*)d_out;

    size_t proj_smem = (size_t)(3 * 128 * HS + 128 * WTS) * sizeof(__half);  // 110592
    cudaFuncSetAttribute(proj_tc, cudaFuncAttributeMaxDynamicSharedMemorySize, (int)proj_smem);
    proj_tc<<<NTOK / 128, 256, proj_smem>>>(z, ln_w, ln_b, w_tri, wq, wk, wv, wg);

    size_t att_smem = (size_t)(2 * NSEQ * KSS) * sizeof(__half) + NSEQ * sizeof(float); // 62976
    cudaFuncSetAttribute(attn_tc, cudaFuncAttributeMaxDynamicSharedMemorySize, (int)att_smem);
    dim3 ga(NSEQ, NH);
    attn_tc<<<ga, 256, att_smem>>>(mask);

    size_t out_smem = (size_t)(2 * 128 * HS) * sizeof(__half);   // 69632
    cudaFuncSetAttribute(out_tc, cudaFuncAttributeMaxDynamicSharedMemorySize, (int)out_smem);
    out_tc<<<NTOK / 128, 256, out_smem>>>(wo, out);
}